// round 13
// baseline (speedup 1.0000x reference)
#include <cuda_runtime.h>
#include <cuda_bf16.h>

// Quaternion tensor product — CONVERGED FINAL (pinned).
//
// At the HBM wall: 1.61 GB information-minimal traffic @ ~7.1 TB/s (89% of
// 8 TB/s spec), dram__cycles_active ~90%, compute pipes <7%, issue ~9%.
//
// Exhaustive sweep (R2-R12): bandwidth invariant across occupancy 28-59%,
// per-warp MLP 8-16, 128/256-bit accesses, block 256/512, thread-level R/W
// phasing; streaming cache hints +1.5% (kept); persistent grid -8% (loop
// control serializes load bursts — flat short CTAs win). Five repeat
// measurements of this config: 228.1-229.3us (sigma ~0.5us).
//
// Config: one thread per (batch, float4 channel-group); 8 independent
// front-batched __ldcs (warp = 512B contiguous per load, MLP=8); register
// Hamilton product; 4 early __stcs. 48 regs, flat one-shot grid 32768x256.

__global__ __launch_bounds__(256) void quat_tp_kernel(
    const float4* __restrict__ in0,
    const float4* __restrict__ in1,
    float4* __restrict__ out)
{
    unsigned int idx = blockIdx.x * 256u + threadIdx.x;
    // batch = idx >> 5, group = idx & 31; base (float4 units) = batch*128 + group
    unsigned int base = ((idx >> 5) << 7) | (idx & 31u);

    // Front-batch all 8 independent loads (MLP=8), streaming (evict-first).
    float4 a0 = __ldcs(in0 + base);
    float4 a1 = __ldcs(in0 + base + 32);
    float4 a2 = __ldcs(in0 + base + 64);
    float4 a3 = __ldcs(in0 + base + 96);
    float4 b0 = __ldcs(in1 + base);
    float4 b1 = __ldcs(in1 + base + 32);
    float4 b2 = __ldcs(in1 + base + 64);
    float4 b3 = __ldcs(in1 + base + 96);

    float4 o;

    // o0 = a0*b0 - a1*b1 - a2*b2 - a3*b3
    o.x = a0.x*b0.x - a1.x*b1.x - a2.x*b2.x - a3.x*b3.x;
    o.y = a0.y*b0.y - a1.y*b1.y - a2.y*b2.y - a3.y*b3.y;
    o.z = a0.z*b0.z - a1.z*b1.z - a2.z*b2.z - a3.z*b3.z;
    o.w = a0.w*b0.w - a1.w*b1.w - a2.w*b2.w - a3.w*b3.w;
    __stcs(out + base, o);

    // o1 = a0*b1 + a1*b0 + a2*b3 - a3*b2
    o.x = a0.x*b1.x + a1.x*b0.x + a2.x*b3.x - a3.x*b2.x;
    o.y = a0.y*b1.y + a1.y*b0.y + a2.y*b3.y - a3.y*b2.y;
    o.z = a0.z*b1.z + a1.z*b0.z + a2.z*b3.z - a3.z*b2.z;
    o.w = a0.w*b1.w + a1.w*b0.w + a2.w*b3.w - a3.w*b2.w;
    __stcs(out + base + 32, o);

    // o2 = a0*b2 - a1*b3 + a2*b0 + a3*b1
    o.x = a0.x*b2.x - a1.x*b3.x + a2.x*b0.x + a3.x*b1.x;
    o.y = a0.y*b2.y - a1.y*b3.y + a2.y*b0.y + a3.y*b1.y;
    o.z = a0.z*b2.z - a1.z*b3.z + a2.z*b0.z + a3.z*b1.z;
    o.w = a0.w*b2.w - a1.w*b3.w + a2.w*b0.w + a3.w*b1.w;
    __stcs(out + base + 64, o);

    // o3 = a0*b3 + a1*b2 - a2*b1 + a3*b0
    o.x = a0.x*b3.x + a1.x*b2.x - a2.x*b1.x + a3.x*b0.x;
    o.y = a0.y*b3.y + a1.y*b2.y - a2.y*b1.y + a3.y*b0.y;
    o.z = a0.z*b3.z + a1.z*b2.z - a2.z*b1.z + a3.z*b0.z;
    o.w = a0.w*b3.w + a1.w*b2.w - a2.w*b1.w + a3.w*b0.w;
    __stcs(out + base + 96, o);
}

extern "C" void kernel_launch(void* const* d_in, const int* in_sizes, int n_in,
                              void* d_out, int out_size) {
    const float4* in0 = (const float4*)d_in[0];
    const float4* in1 = (const float4*)d_in[1];
    float4* out = (float4*)d_out;

    // threads = B * 32 = out_size / 16  (out_size = B*512 floats)
    unsigned int threads_total = (unsigned int)((unsigned long long)out_size / 16ull);
    unsigned int grid = (threads_total + 255u) / 256u;
    quat_tp_kernel<<<grid, 256>>>(in0, in1, out);
}

// round 14
// speedup vs baseline: 1.0034x; 1.0034x over previous
#include <cuda_runtime.h>
#include <cuda_bf16.h>

// Quaternion tensor product — converged at HBM wall (~7.1 TB/s, 89% spec).
// R14 micro-probe: interleave in0/in1 load issue order (a0,b0,a1,b1,...)
// to pair the two address streams adjacently in the LSU/LTS queues (bank-
// group overlap). Otherwise identical to the pinned R2 config: float4,
// MLP=8 front-batched __ldcs, early __stcs, blk256, flat grid, 48 regs.

__global__ __launch_bounds__(256) void quat_tp_kernel(
    const float4* __restrict__ in0,
    const float4* __restrict__ in1,
    float4* __restrict__ out)
{
    unsigned int idx = blockIdx.x * 256u + threadIdx.x;
    // batch = idx >> 5, group = idx & 31; base (float4 units) = batch*128 + group
    unsigned int base = ((idx >> 5) << 7) | (idx & 31u);

    // 8 independent streaming loads, issue-interleaved across the two buffers.
    float4 a0 = __ldcs(in0 + base);
    float4 b0 = __ldcs(in1 + base);
    float4 a1 = __ldcs(in0 + base + 32);
    float4 b1 = __ldcs(in1 + base + 32);
    float4 a2 = __ldcs(in0 + base + 64);
    float4 b2 = __ldcs(in1 + base + 64);
    float4 a3 = __ldcs(in0 + base + 96);
    float4 b3 = __ldcs(in1 + base + 96);

    float4 o;

    // o0 = a0*b0 - a1*b1 - a2*b2 - a3*b3
    o.x = a0.x*b0.x - a1.x*b1.x - a2.x*b2.x - a3.x*b3.x;
    o.y = a0.y*b0.y - a1.y*b1.y - a2.y*b2.y - a3.y*b3.y;
    o.z = a0.z*b0.z - a1.z*b1.z - a2.z*b2.z - a3.z*b3.z;
    o.w = a0.w*b0.w - a1.w*b1.w - a2.w*b2.w - a3.w*b3.w;
    __stcs(out + base, o);

    // o1 = a0*b1 + a1*b0 + a2*b3 - a3*b2
    o.x = a0.x*b1.x + a1.x*b0.x + a2.x*b3.x - a3.x*b2.x;
    o.y = a0.y*b1.y + a1.y*b0.y + a2.y*b3.y - a3.y*b2.y;
    o.z = a0.z*b1.z + a1.z*b0.z + a2.z*b3.z - a3.z*b2.z;
    o.w = a0.w*b1.w + a1.w*b0.w + a2.w*b3.w - a3.w*b2.w;
    __stcs(out + base + 32, o);

    // o2 = a0*b2 - a1*b3 + a2*b0 + a3*b1
    o.x = a0.x*b2.x - a1.x*b3.x + a2.x*b0.x + a3.x*b1.x;
    o.y = a0.y*b2.y - a1.y*b3.y + a2.y*b0.y + a3.y*b1.y;
    o.z = a0.z*b2.z - a1.z*b3.z + a2.z*b0.z + a3.z*b1.z;
    o.w = a0.w*b2.w - a1.w*b3.w + a2.w*b0.w + a3.w*b1.w;
    __stcs(out + base + 64, o);

    // o3 = a0*b3 + a1*b2 - a2*b1 + a3*b0
    o.x = a0.x*b3.x + a1.x*b2.x - a2.x*b1.x + a3.x*b0.x;
    o.y = a0.y*b3.y + a1.y*b2.y - a2.y*b1.y + a3.y*b0.y;
    o.z = a0.z*b3.z + a1.z*b2.z - a2.z*b1.z + a3.z*b0.z;
    o.w = a0.w*b3.w + a1.w*b2.w - a2.w*b1.w + a3.w*b0.w;
    __stcs(out + base + 96, o);
}

extern "C" void kernel_launch(void* const* d_in, const int* in_sizes, int n_in,
                              void* d_out, int out_size) {
    const float4* in0 = (const float4*)d_in[0];
    const float4* in1 = (const float4*)d_in[1];
    float4* out = (float4*)d_out;

    // threads = B * 32 = out_size / 16  (out_size = B*512 floats)
    unsigned int threads_total = (unsigned int)((unsigned long long)out_size / 16ull);
    unsigned int grid = (threads_total + 255u) / 256u;
    quat_tp_kernel<<<grid, 256>>>(in0, in1, out);
}